// round 1
// baseline (speedup 1.0000x reference)
#include <cuda_runtime.h>
#include <math.h>

#define B_ 4
#define S_ 4096
#define D_ 512
#define SCALE_ 0.125f

// Scratch for Q, K, V projections (32 MB each)
__device__ float g_Q[B_ * S_ * D_];
__device__ float g_K[B_ * S_ * D_];
__device__ float g_V[B_ * S_ * D_];

// ---------------------------------------------------------------------------
// QKV projection: y[m,n] = sum_k x[m,k] * W[n,k] + b[n]
// M = B*S = 16384, N = K = 512. Classic 128x128 tile, 8x8 microtile, BK=8.
// ---------------------------------------------------------------------------
__global__ void __launch_bounds__(256) qkv_gemm_kernel(
    const float* __restrict__ x,
    const float* __restrict__ Wq, const float* __restrict__ bq,
    const float* __restrict__ Wk, const float* __restrict__ bk,
    const float* __restrict__ Wv, const float* __restrict__ bv)
{
    __shared__ float As[8][128];
    __shared__ float Bs[8][128];

    const float* W; const float* bias; float* out;
    if (blockIdx.z == 0)      { W = Wq; bias = bq; out = g_Q; }
    else if (blockIdx.z == 1) { W = Wk; bias = bk; out = g_K; }
    else                      { W = Wv; bias = bv; out = g_V; }

    const int tid = threadIdx.x;
    const int m0 = blockIdx.y * 128;
    const int n0 = blockIdx.x * 128;

    const int lr = tid >> 1;          // 0..127 : row loaded
    const int lc = (tid & 1) * 4;     // 0 or 4 : k-offset (float4)
    const int tx = tid & 15;          // microtile col group
    const int ty = tid >> 4;          // microtile row group

    const float* Ap = x + (size_t)(m0 + lr) * D_ + lc;
    const float* Bp = W + (size_t)(n0 + lr) * D_ + lc;

    float acc[8][8];
#pragma unroll
    for (int i = 0; i < 8; i++)
#pragma unroll
        for (int j = 0; j < 8; j++) acc[i][j] = 0.f;

    for (int k0 = 0; k0 < D_; k0 += 8) {
        float4 a4 = *(const float4*)(Ap + k0);
        float4 b4 = *(const float4*)(Bp + k0);
        As[lc + 0][lr] = a4.x; As[lc + 1][lr] = a4.y;
        As[lc + 2][lr] = a4.z; As[lc + 3][lr] = a4.w;
        Bs[lc + 0][lr] = b4.x; Bs[lc + 1][lr] = b4.y;
        Bs[lc + 2][lr] = b4.z; Bs[lc + 3][lr] = b4.w;
        __syncthreads();
#pragma unroll
        for (int kk = 0; kk < 8; kk++) {
            float a[8], b[8];
            *(float4*)&a[0] = *(const float4*)&As[kk][ty * 8];
            *(float4*)&a[4] = *(const float4*)&As[kk][ty * 8 + 4];
            *(float4*)&b[0] = *(const float4*)&Bs[kk][tx * 8];
            *(float4*)&b[4] = *(const float4*)&Bs[kk][tx * 8 + 4];
#pragma unroll
            for (int i = 0; i < 8; i++)
#pragma unroll
                for (int j = 0; j < 8; j++)
                    acc[i][j] = fmaf(a[i], b[j], acc[i][j]);
        }
        __syncthreads();
    }

    const int n = n0 + tx * 8;
#pragma unroll
    for (int i = 0; i < 8; i++) {
        float* orow = out + (size_t)(m0 + ty * 8 + i) * D_ + n;
        float4 o0, o1;
        o0.x = acc[i][0] + bias[n + 0]; o0.y = acc[i][1] + bias[n + 1];
        o0.z = acc[i][2] + bias[n + 2]; o0.w = acc[i][3] + bias[n + 3];
        o1.x = acc[i][4] + bias[n + 4]; o1.y = acc[i][5] + bias[n + 5];
        o1.z = acc[i][6] + bias[n + 6]; o1.w = acc[i][7] + bias[n + 7];
        ((float4*)orow)[0] = o0;
        ((float4*)orow)[1] = o1;
    }
}

// ---------------------------------------------------------------------------
// Flash attention, causal, fp32. BM=BN=64, 512 threads, 1 CTA/SM.
// Q tile (pre-scaled) resident in smem; K streamed in 64-wide d-chunks;
// V streamed in 16-row chunks; O accumulator in registers (64/thread).
// ---------------------------------------------------------------------------
#define FBM 64
#define FBN 64
#define FTH 512
#define QS_STR 516     // 512 + 4 pad
#define KC_STR 68      // 64 + 4 pad
#define VC_STR 544     // 8 groups of (64 + 4 pad)
#define SS_STR 66      // 64 + 2 pad

#define SM_QS  0
#define SM_KC  33024   // 64*516
#define SM_VC  37376   // + 64*68
#define SM_SS  46080   // + 16*544
#define SM_M   50304   // + 64*66
#define SM_L   50368
#define SM_A   50432
#define SM_TOTF 50496  // floats -> 201984 bytes

#define NEG_INF (-1e30f)

#define DOT4(ACC, QV, KV)                    \
    ACC = fmaf((QV).x, (KV).x, ACC);         \
    ACC = fmaf((QV).y, (KV).y, ACC);         \
    ACC = fmaf((QV).z, (KV).z, ACC);         \
    ACC = fmaf((QV).w, (KV).w, ACC);

__global__ void __launch_bounds__(512, 1) flash_attn_kernel(float* __restrict__ out)
{
    extern __shared__ float sm[];
    float* Qs  = sm + SM_QS;
    float* Kc  = sm + SM_KC;
    float* Vc  = sm + SM_VC;
    float* Ssm = sm + SM_SS;
    float* mrow = sm + SM_M;
    float* lrow = sm + SM_L;
    float* arow = sm + SM_A;

    const int t  = threadIdx.x;
    const int b  = blockIdx.x;                       // batch
    const int qt = (S_ / FBM - 1) - blockIdx.y;      // heavy query tiles first

    const float* Qg     = g_Q + ((size_t)b * S_ + (size_t)qt * FBM) * D_;
    const float* Kgbase = g_K + (size_t)b * S_ * D_;
    const float* Vgbase = g_V + (size_t)b * S_ * D_;

    // Load Q tile into smem, folding the 1/8 score scale in.
    for (int i = t; i < FBM * (D_ / 4); i += FTH) {
        int r  = i >> 7;       // /128 float4-per-row
        int c4 = i & 127;
        float4 v = ((const float4*)(Qg + (size_t)r * D_))[c4];
        v.x *= SCALE_; v.y *= SCALE_; v.z *= SCALE_; v.w *= SCALE_;
        *(float4*)(Qs + r * QS_STR + c4 * 4) = v;
    }
    if (t < FBM) { mrow[t] = NEG_INF; lrow[t] = 0.f; }

    float Oacc[64];
#pragma unroll
    for (int u = 0; u < 64; u++) Oacc[u] = 0.f;

    const int tr = t & 15;     // score rows: tr, tr+16, tr+32, tr+48
    const int tc = t >> 4;     // score cols: 2*tc, 2*tc+1
    const int r  = t >> 3;     // owned output row (0..63)
    const int c8 = t & 7;      // owned output col slice (c8*64 .. +63)

    __syncthreads();

    for (int kt = 0; kt <= qt; kt++) {
        const float* Kg = Kgbase + (size_t)kt * FBN * D_;

        // ---------------- scores: S = (Q*SCALE) . K^T ----------------
        float s00 = 0.f, s01 = 0.f, s10 = 0.f, s11 = 0.f;
        float s20 = 0.f, s21 = 0.f, s30 = 0.f, s31 = 0.f;
        for (int dc = 0; dc < 8; dc++) {
            for (int i = t; i < FBN * 16; i += FTH) {   // K chunk [64][64]
                int rr = i >> 4;
                int c4 = i & 15;
                float4 v = ((const float4*)(Kg + (size_t)rr * D_ + dc * 64))[c4];
                *(float4*)(Kc + rr * KC_STR + c4 * 4) = v;
            }
            __syncthreads();
#pragma unroll 4
            for (int dq = 0; dq < 16; dq++) {
                const int qo = dc * 64 + dq * 4;
                float4 q0 = *(const float4*)(Qs + (tr     ) * QS_STR + qo);
                float4 q1 = *(const float4*)(Qs + (tr + 16) * QS_STR + qo);
                float4 q2 = *(const float4*)(Qs + (tr + 32) * QS_STR + qo);
                float4 q3 = *(const float4*)(Qs + (tr + 48) * QS_STR + qo);
                float4 k0 = *(const float4*)(Kc + (2 * tc    ) * KC_STR + dq * 4);
                float4 k1 = *(const float4*)(Kc + (2 * tc + 1) * KC_STR + dq * 4);
                DOT4(s00, q0, k0); DOT4(s01, q0, k1);
                DOT4(s10, q1, k0); DOT4(s11, q1, k1);
                DOT4(s20, q2, k0); DOT4(s21, q2, k1);
                DOT4(s30, q3, k0); DOT4(s31, q3, k1);
            }
            __syncthreads();
        }
        Ssm[(tr     ) * SS_STR + 2 * tc + 0] = s00;
        Ssm[(tr     ) * SS_STR + 2 * tc + 1] = s01;
        Ssm[(tr + 16) * SS_STR + 2 * tc + 0] = s10;
        Ssm[(tr + 16) * SS_STR + 2 * tc + 1] = s11;
        Ssm[(tr + 32) * SS_STR + 2 * tc + 0] = s20;
        Ssm[(tr + 32) * SS_STR + 2 * tc + 1] = s21;
        Ssm[(tr + 48) * SS_STR + 2 * tc + 0] = s30;
        Ssm[(tr + 48) * SS_STR + 2 * tc + 1] = s31;
        __syncthreads();

        // ---------------- online softmax update ----------------
        const bool diag = (kt == qt);
        float sv[8];
        float lm = NEG_INF;
#pragma unroll
        for (int u = 0; u < 8; u++) {
            int j = c8 * 8 + u;
            float s = Ssm[r * SS_STR + j];
            if (diag && j > r) s = NEG_INF;
            sv[u] = s;
            lm = fmaxf(lm, s);
        }
#pragma unroll
        for (int off = 4; off > 0; off >>= 1)
            lm = fmaxf(lm, __shfl_xor_sync(0xffffffffu, lm, off));
        float mold = mrow[r];
        float mnew = fmaxf(mold, lm);
        float ls = 0.f;
#pragma unroll
        for (int u = 0; u < 8; u++) {
            float p = __expf(sv[u] - mnew);
            Ssm[r * SS_STR + c8 * 8 + u] = p;
            ls += p;
        }
#pragma unroll
        for (int off = 4; off > 0; off >>= 1)
            ls += __shfl_xor_sync(0xffffffffu, ls, off);
        if (c8 == 0) {
            float al = __expf(mold - mnew);
            arow[r] = al;
            lrow[r] = lrow[r] * al + ls;
            mrow[r] = mnew;
        }
        __syncthreads();

        // ---------------- PV: O = O*alpha + P.V ----------------
        float al = arow[r];
#pragma unroll
        for (int u = 0; u < 64; u++) Oacc[u] *= al;

        const float* Vg = Vgbase + (size_t)kt * FBN * D_;
        for (int vcs = 0; vcs < 4; vcs++) {
            for (int i = t; i < 16 * 128; i += FTH) {   // V chunk [16][512], group-padded
                int rr = i >> 7;
                int c4 = i & 127;
                float4 v = ((const float4*)(Vg + (size_t)(vcs * 16 + rr) * D_))[c4];
                *(float4*)(Vc + rr * VC_STR + c4 * 4 + ((c4 >> 4) << 2)) = v;
            }
            __syncthreads();
#pragma unroll 2
            for (int kk = 0; kk < 16; kk++) {
                float p = Ssm[r * SS_STR + vcs * 16 + kk];
                const float4* Vrow = (const float4*)(Vc + kk * VC_STR + c8 * 68);
#pragma unroll
                for (int u = 0; u < 16; u++) {
                    float4 v = Vrow[u];
                    Oacc[4 * u + 0] = fmaf(p, v.x, Oacc[4 * u + 0]);
                    Oacc[4 * u + 1] = fmaf(p, v.y, Oacc[4 * u + 1]);
                    Oacc[4 * u + 2] = fmaf(p, v.z, Oacc[4 * u + 2]);
                    Oacc[4 * u + 3] = fmaf(p, v.w, Oacc[4 * u + 3]);
                }
            }
            __syncthreads();
        }
    }

    // ---------------- write output ----------------
    float inv = 1.f / lrow[r];
    float* Og = out + ((size_t)b * S_ + (size_t)qt * FBM + r) * D_ + c8 * 64;
#pragma unroll
    for (int u = 0; u < 16; u++) {
        float4 v;
        v.x = Oacc[4 * u + 0] * inv;
        v.y = Oacc[4 * u + 1] * inv;
        v.z = Oacc[4 * u + 2] * inv;
        v.w = Oacc[4 * u + 3] * inv;
        ((float4*)Og)[u] = v;
    }
}

// ---------------------------------------------------------------------------
extern "C" void kernel_launch(void* const* d_in, const int* in_sizes, int n_in,
                              void* d_out, int out_size)
{
    const float* x  = (const float*)d_in[0];
    const float* Wq = (const float*)d_in[1];
    const float* bq = (const float*)d_in[2];
    const float* Wk = (const float*)d_in[3];
    const float* bk = (const float*)d_in[4];
    const float* Wv = (const float*)d_in[5];
    const float* bv = (const float*)d_in[6];
    float* out = (float*)d_out;

    (void)in_sizes; (void)n_in; (void)out_size;

    // QKV projections: grid (N/128, M/128, 3)
    qkv_gemm_kernel<<<dim3(D_ / 128, (B_ * S_) / 128, 3), 256>>>(
        x, Wq, bq, Wk, bk, Wv, bv);

    // Flash attention: grid (batch, query-tiles reversed)
    const int smem_bytes = SM_TOTF * (int)sizeof(float);   // 201984
    cudaFuncSetAttribute(flash_attn_kernel,
                         cudaFuncAttributeMaxDynamicSharedMemorySize, smem_bytes);
    flash_attn_kernel<<<dim3(B_, S_ / FBM), FTH, smem_bytes>>>(out);
}